// round 10
// baseline (speedup 1.0000x reference)
#include <cuda_runtime.h>

// Router: logits = x @ wg^T + gr @ gm^T ; std-normalized softmax; top-2;
// mask expert E-1; renormalize.
// Output layout (float32): [gates 2T | indices 2T | logits 8T]
//
// R10: minimize LSU cycles/byte (the validated limiter: LDG.128 ~4cy,
// LDGSTS 8cy, LDS conflict-priced). NT=8 octet-split + cp.async ring of
// 2KB half-stages (DEPTH=4, fine-grained lead) + wg rows padded to 513
// chunks so the 4 octets (4 different experts) hit disjoint smem banks:
// wg LDS 4cy -> 1cy. L1 budget 52cy/2KB ~= 13.3us < 17us DRAM floor.

constexpr int D       = 2048;
constexpr int E       = 8;
constexpr int NT      = 8;            // tokens per warp
constexpr int THREADS = 448;          // 14 warps, 1 CTA/SM
constexpr int WARPS   = THREADS / 32;
constexpr int CHUNKS  = D / 4;        // 16B chunks per row = 512
constexpr int CHUNKW  = CHUNKS + 1;   // padded wg row stride (bank-spread)
constexpr int HALVES  = 32;           // 2KB half-stages per unit (16 chunks ea)
constexpr int DEPTH   = 4;            // ring depth (half-stages)
constexpr int GRID    = 148;

// smem floats: wg [E][CHUNKW*4] | gm [64] | ring [WARPS*DEPTH*512]
constexpr int WG_FLOATS   = E * CHUNKW * 4;                   // 16416
constexpr int GM_OFF      = WG_FLOATS;                        // 16416
constexpr int RING_OFF    = WG_FLOATS + 64;                   // 16480
constexpr int RING_FLOATS = WARPS * DEPTH * 512;              // 28672
constexpr int SMEM_BYTES  = (RING_OFF + RING_FLOATS) * 4;     // 180608 B

__device__ __forceinline__ unsigned long long ffma2(unsigned long long a,
                                                    unsigned long long b,
                                                    unsigned long long c) {
    unsigned long long d;
    asm("fma.rn.f32x2 %0, %1, %2, %3;" : "=l"(d) : "l"(a), "l"(b), "l"(c));
    return d;
}

__device__ __forceinline__ float pairsum(unsigned long long v) {
    float2 f;
    f.x = __uint_as_float((unsigned int)(v & 0xffffffffull));
    f.y = __uint_as_float((unsigned int)(v >> 32));
    return f.x + f.y;
}

__device__ __forceinline__ void cp16(unsigned int dst_smem, const void* src) {
    asm volatile("cp.async.cg.shared.global [%0], [%1], 16;\n"
                 :: "r"(dst_smem), "l"(src) : "memory");
}

__global__ void __launch_bounds__(THREADS, 1)
router_kernel(const float* __restrict__ x,
              const float* __restrict__ wg,
              const float* __restrict__ gm,
              const float* __restrict__ gr,
              float* __restrict__ out_gates,
              float* __restrict__ out_idx,
              float* __restrict__ out_logits,
              int nGroups) {
    extern __shared__ float smem[];
    float4* s_wg4 = reinterpret_cast<float4*>(smem);   // [E][CHUNKW] float4s
    float*  s_gm  = smem + GM_OFF;

    // Stage wg with padded row stride (bank-conflict-free octet reads).
    const float4* wg4 = reinterpret_cast<const float4*>(wg);
    for (int i = threadIdx.x; i < E * CHUNKS; i += THREADS) {
        int row = i >> 9;           // /CHUNKS
        int col = i & (CHUNKS - 1);
        s_wg4[row * CHUNKW + col] = wg4[i];
    }
    if (threadIdx.x < E * E) s_gm[threadIdx.x] = gm[threadIdx.x];
    __syncthreads();

    const ulonglong2* s_w2 = reinterpret_cast<const ulonglong2*>(smem);

    const int lane  = threadIdx.x & 31;
    const int wid   = threadIdx.x >> 5;
    const int l8    = lane & 7;         // position within octet
    const int e0    = (lane >> 3) * 2;  // this octet's first expert
    const int tokOp = lane >> 4;        // 0/1: which token of the pair to copy
    const int c16   = lane & 15;        // chunk-in-stage this lane copies

    // Per-warp ring: DEPTH half-stages of 2KB (8 tokens x 16 chunks x 16B).
    float* ring = smem + RING_OFF + wid * (DEPTH * 512);
    const unsigned int ring_addr = (unsigned int)__cvta_generic_to_shared(ring);
    const ulonglong2* ring_u2 = reinterpret_cast<const ulonglong2*>(ring);

    const int g = blockIdx.x + gridDim.x * wid;   // one unit per warp

    if (g < nGroups) {
        const int t0 = g * NT;
        const char* xrow = reinterpret_cast<const char*>(x + (size_t)t0 * D);
        // copy source for half-stage hh, op o: token 2o+tokOp,
        // chunk hh*16 + c16.

        unsigned long long acc[NT][2];
        #pragma unroll
        for (int j = 0; j < NT; j++) { acc[j][0] = 0ull; acc[j][1] = 0ull; }

        // ---- prologue: half-stages 0..DEPTH-1 ----
        #pragma unroll
        for (int s = 0; s < DEPTH; s++) {
            #pragma unroll
            for (int o = 0; o < 4; o++) {
                const int tok = 2 * o + tokOp;
                cp16(ring_addr + s * 2048 + tok * 256 + c16 * 16,
                     xrow + (size_t)tok * (D * 4) + (s * 16 + c16) * 16);
            }
            asm volatile("cp.async.commit_group;\n" ::: "memory");
        }

        #pragma unroll 4
        for (int hh = 0; hh < HALVES; hh++) {
            // pending <= DEPTH-1  =>  half-stage hh has landed
            asm volatile("cp.async.wait_group %0;\n" :: "n"(DEPTH - 1) : "memory");

            const int slot = hh & (DEPTH - 1);
            const ulonglong2* xs = ring_u2 + slot * 128;  // 2048B/16

            // snapshot x to registers BEFORE refilling this slot
            ulonglong2 xv[16];
            #pragma unroll
            for (int kk = 0; kk < 2; kk++)
                #pragma unroll
                for (int j = 0; j < NT; j++)
                    xv[kk * 8 + j] = xs[j * 16 + kk * 8 + l8];

            // refill slot with half-stage hh+DEPTH
            const int s = hh + DEPTH;
            if (s < HALVES) {
                #pragma unroll
                for (int o = 0; o < 4; o++) {
                    const int tok = 2 * o + tokOp;
                    cp16(ring_addr + slot * 2048 + tok * 256 + c16 * 16,
                         xrow + (size_t)tok * (D * 4) + (s * 16 + c16) * 16);
                }
            }
            asm volatile("cp.async.commit_group;\n" ::: "memory");

            #pragma unroll
            for (int kk = 0; kk < 2; kk++) {
                const int c = hh * 16 + kk * 8 + l8;
                ulonglong2 wv0 = s_w2[e0 * CHUNKW + c];
                ulonglong2 wv1 = s_w2[(e0 + 1) * CHUNKW + c];
                #pragma unroll
                for (int j = 0; j < NT; j++) {
                    ulonglong2 xj = xv[kk * 8 + j];
                    acc[j][0] = ffma2(xj.x, wv0.x, acc[j][0]);
                    acc[j][0] = ffma2(xj.y, wv0.y, acc[j][0]);
                    acc[j][1] = ffma2(xj.x, wv1.x, acc[j][1]);
                    acc[j][1] = ffma2(xj.y, wv1.y, acc[j][1]);
                }
            }
        }

        // ---- reduce within each octet (3-step butterfly) ----
        float red[NT][2];
        #pragma unroll
        for (int j = 0; j < NT; j++) {
            #pragma unroll
            for (int e = 0; e < 2; e++) {
                float s = pairsum(acc[j][e]);
                s += __shfl_xor_sync(0xffffffffu, s, 4);
                s += __shfl_xor_sync(0xffffffffu, s, 2);
                s += __shfl_xor_sync(0xffffffffu, s, 1);
                red[j][e] = s;
            }
        }

        // lane (octet q, l8=j) keeps token t0+j's logits for experts
        // 2q, 2q+1; gather all 8 experts onto lanes 0-7.
        float s0 = red[0][0], s1 = red[0][1];
        #pragma unroll
        for (int jj = 1; jj < NT; jj++)
            if (l8 == jj) { s0 = red[jj][0]; s1 = red[jj][1]; }

        float logit[E];
        logit[0] = s0;
        logit[1] = s1;
        logit[2] = __shfl_sync(0xffffffffu, s0, l8 + 8);
        logit[3] = __shfl_sync(0xffffffffu, s1, l8 + 8);
        logit[4] = __shfl_sync(0xffffffffu, s0, l8 + 16);
        logit[5] = __shfl_sync(0xffffffffu, s1, l8 + 16);
        logit[6] = __shfl_sync(0xffffffffu, s0, l8 + 24);
        logit[7] = __shfl_sync(0xffffffffu, s1, l8 + 24);

        if (lane < NT) {
            const int t = t0 + lane;

            float4 g0 = __ldg(reinterpret_cast<const float4*>(gr + (size_t)t * E));
            float4 g1 = __ldg(reinterpret_cast<const float4*>(gr + (size_t)t * E + 4));
            float grv[8] = {g0.x, g0.y, g0.z, g0.w, g1.x, g1.y, g1.z, g1.w};
            float lg[E];
            #pragma unroll
            for (int f = 0; f < E; f++) {
                float s = logit[f];
                #pragma unroll
                for (int e = 0; e < E; e++) s = fmaf(grv[e], s_gm[f * E + e], s);
                lg[f] = s;
            }

            // unbiased std (ddof=1) over E=8
            float mean = 0.f;
            #pragma unroll
            for (int f = 0; f < E; f++) mean += lg[f];
            mean *= (1.f / E);
            float var = 0.f;
            #pragma unroll
            for (int f = 0; f < E; f++) {
                float d = lg[f] - mean;
                var = fmaf(d, d, var);
            }
            float inv_std = rsqrtf(var * (1.f / (E - 1)));

            float z[E], m = -3.402823466e+38f;
            #pragma unroll
            for (int f = 0; f < E; f++) {
                z[f] = lg[f] * inv_std;
                m = fmaxf(m, z[f]);
            }
            float p[E], psum = 0.f;
            #pragma unroll
            for (int f = 0; f < E; f++) {
                p[f] = __expf(z[f] - m);
                psum += p[f];
            }
            float inv_psum = 1.f / psum;
            #pragma unroll
            for (int f = 0; f < E; f++) p[f] *= inv_psum;

            // stable top-2 (descending, lower index wins ties)
            int i1 = 0; float v1 = p[0];
            #pragma unroll
            for (int f = 1; f < E; f++)
                if (p[f] > v1) { v1 = p[f]; i1 = f; }
            int i2; float v2;
            if (i1 == 0) { i2 = 1; v2 = p[1]; } else { i2 = 0; v2 = p[0]; }
            #pragma unroll
            for (int f = 1; f < E; f++)
                if (f != i1 && p[f] > v2) { v2 = p[f]; i2 = f; }

            float gg1 = (i1 == E - 1) ? 0.f : v1;
            float gg2 = (i2 == E - 1) ? 0.f : v2;
            float inv_s = 1.f / (gg1 + gg2);
            gg1 *= inv_s; gg2 *= inv_s;

            float2 gpair; gpair.x = gg1; gpair.y = gg2;
            *reinterpret_cast<float2*>(out_gates + (size_t)2 * t) = gpair;
            float2 ipair; ipair.x = (float)i1; ipair.y = (float)i2;
            *reinterpret_cast<float2*>(out_idx + (size_t)2 * t) = ipair;

            float4 L0; L0.x = lg[0]; L0.y = lg[1]; L0.z = lg[2]; L0.w = lg[3];
            float4 L1; L1.x = lg[4]; L1.y = lg[5]; L1.z = lg[6]; L1.w = lg[7];
            float4* olr = reinterpret_cast<float4*>(out_logits + (size_t)t * E);
            olr[0] = L0;
            olr[1] = L1;
        }

        asm volatile("cp.async.wait_group 0;\n" ::: "memory");
    }
}

extern "C" void kernel_launch(void* const* d_in, const int* in_sizes, int n_in,
                              void* d_out, int out_size) {
    const float* x  = (const float*)d_in[0];   // [T, D]
    const float* wg = (const float*)d_in[1];   // [E, D]
    const float* gm = (const float*)d_in[2];   // [E, E]
    const float* gr = (const float*)d_in[3];   // [T, E]

    const int T = in_sizes[0] / D;
    float* out       = (float*)d_out;
    float* out_gates = out;                       // [T,2]
    float* out_idx   = out + (size_t)2 * T;       // [T,2] as float
    float* out_logit = out + (size_t)4 * T;       // [T,8]

    cudaFuncSetAttribute(router_kernel,
                         cudaFuncAttributeMaxDynamicSharedMemorySize,
                         SMEM_BYTES);

    const int nGroups = T / NT;                   // 2048
    router_kernel<<<GRID, THREADS, SMEM_BYTES>>>(x, wg, gm, gr,
                                                 out_gates, out_idx, out_logit,
                                                 nGroups);
}